// round 16
// baseline (speedup 1.0000x reference)
#include <cuda_runtime.h>
#include <cuda_fp16.h>
#include <cstdint>

#define DFULL 256
#define DH    128
#define NMAX  65536
#define KMAX  4096

// ---------------- device scratch (allocation-free rule) ----------------
__device__ float g_zr[(size_t)NMAX * DH];  // z-hat ROW-major [row][feat] (fp32, rescore)
__device__ float g_et[DH * KMAX];   // emb-hat transposed [feat][code] (fp32, rescore)
__device__ float g_z2[NMAX];        // emulated fp32 sum(zhat^2)
__device__ float g_b [KMAX];        // emulated fp32 sum(ehat^2)
__device__ __half g_zh[(size_t)NMAX * DH];  // fp16 z-hat, row-major [row][feat]
__device__ __half g_eh[(size_t)KMAX * DH];  // fp16 e-hat, row-major [code][feat]
__device__ int   g_idx[NMAX];
__device__ int   g_fixlist[NMAX];
__device__ int   g_fixcount;

// ---------------- helpers ----------------
__device__ __forceinline__ void fma2(unsigned long long &c, unsigned long long a, unsigned long long b) {
    asm("fma.rn.f32x2 %0, %1, %2, %0;" : "+l"(c) : "l"(a), "l"(b));
}
__device__ __forceinline__ unsigned long long dup2(float x) {
    unsigned long long r;
    asm("mov.b64 %0, {%1, %1};" : "=l"(r) : "f"(x));
    return r;
}
__device__ __forceinline__ void unpk(unsigned long long v, float &lo, float &hi) {
    asm("mov.b64 {%0, %1}, %2;" : "=f"(lo), "=f"(hi) : "l"(v));
}
__device__ __forceinline__ uint32_t smem_u32(const void* p) {
    uint32_t a;
    asm("{ .reg .u64 t; cvta.to.shared.u64 t, %1; cvt.u32.u64 %0, t; }" : "=r"(a) : "l"(p));
    return a;
}
__device__ __forceinline__ void cp16(uint32_t dst, const void* src) {
    asm volatile("cp.async.cg.shared.global [%0], [%1], 16;" :: "r"(dst), "l"(src));
}
__device__ __forceinline__ void cp4(uint32_t dst, const void* src) {
    asm volatile("cp.async.ca.shared.global [%0], [%1], 4;" :: "r"(dst), "l"(src));
}
__device__ __forceinline__ void ldsm4(uint32_t* r, uint32_t addr) {
    asm volatile("ldmatrix.sync.aligned.m8n8.x4.shared.b16 {%0,%1,%2,%3}, [%4];"
                 : "=r"(r[0]), "=r"(r[1]), "=r"(r[2]), "=r"(r[3]) : "r"(addr));
}
__device__ __forceinline__ void mma16816f(float* c, const uint32_t* a, uint32_t b0, uint32_t b1) {
    asm volatile(
        "mma.sync.aligned.m16n8k16.row.col.f32.f16.f16.f32 "
        "{%0,%1,%2,%3}, {%4,%5,%6,%7}, {%8,%9}, {%0,%1,%2,%3};"
        : "+f"(c[0]), "+f"(c[1]), "+f"(c[2]), "+f"(c[3])
        : "r"(a[0]), "r"(a[1]), "r"(a[2]), "r"(a[3]), "r"(b0), "r"(b1));
}

// XLA-GPU-style row reduction of squares (numerics from passing round)
__device__ __forceinline__ float warp_sumsq_row(const float* row, int lane) {
    float x0 = row[lane];
    float x1 = row[lane + 32];
    float x2 = row[lane + 64];
    float x3 = row[lane + 96];
    float p = __fmaf_rn(x0, x0, 0.0f);
    p = __fmaf_rn(x1, x1, p);
    p = __fmaf_rn(x2, x2, p);
    p = __fmaf_rn(x3, x3, p);
    p = __fadd_rn(p, __shfl_down_sync(0xffffffffu, p, 16));
    p = __fadd_rn(p, __shfl_down_sync(0xffffffffu, p, 8));
    p = __fadd_rn(p, __shfl_down_sync(0xffffffffu, p, 4));
    p = __fadd_rn(p, __shfl_down_sync(0xffffffffu, p, 2));
    p = __fadd_rn(p, __shfl_down_sync(0xffffffffu, p, 1));
    return p;
}

// ============================================================================
// fused proj kernel (R15 numerics + cp.async double-buffered k-chunks):
// z blocks [0, nbz), emb blocks [nbz, ...). 128-row blocks, thread tile 8x8.
// GEMM chunk buffers: 2 x (Xs[32][132] | Ws[32][132]); reductions reuse SA.
// ============================================================================
__global__ __launch_bounds__(256, 2) void proj_kernel(
    const float* __restrict__ Z, const float* __restrict__ E,
    const float* __restrict__ W, const float* __restrict__ bias,
    int n, int k)
{
    extern __shared__ float SA[];       // 16896 floats
    float* rbuf = SA;                   // [128][128], reused after GEMM
    float* rn = SA + 16384;             // [128]

    const int tid = threadIdx.x;
    const int tx = tid & 15, ty = tid >> 4;
    const int warp = tid >> 5, lane = tid & 31;
    const uint32_t sb = smem_u32(SA);

    const int nbz = n / 128;
    const bool is_z = (blockIdx.x < (unsigned)nbz);
    const float* X = is_z ? Z : E;
    float* aux   = is_z ? g_z2 : g_b;
    __half* oh   = is_z ? g_zh : g_eh;
    const int m0 = (is_z ? blockIdx.x : (blockIdx.x - nbz)) * 128;

    if (blockIdx.x == 0 && tid == 0) g_fixcount = 0;

    unsigned long long acc[8][4];
    #pragma unroll
    for (int i = 0; i < 8; i++)
        #pragma unroll
        for (int j = 0; j < 4; j++) acc[i][j] = 0ull;

    // async fill of chunk (32 feats) into buffer b: Xs at b*8448, Ws at +4224
    const int kk0 = tid & 31, q0 = tid >> 5;   // per-thread fixed (kk, q-base)
    // prologue: chunk 0 -> buf 0
    #pragma unroll
    for (int p = 0; p < 16; p++) {
        int idx = tid + p * 256;
        int kk = idx & 31;
        int q  = idx >> 5;
        cp4(sb + (uint32_t)(kk * 132 + q) * 4u,        &X[(size_t)(m0 + q) * 256 + kk]);
        cp4(sb + (uint32_t)(4224 + kk * 132 + q) * 4u, &W[(size_t)q * 256 + kk]);
    }
    asm volatile("cp.async.commit_group;");
    (void)kk0; (void)q0;

    for (int c = 0; c < 8; c++) {
        asm volatile("cp.async.wait_group 0;");
        __syncthreads();

        if (c + 1 < 8) {
            const int k0n = (c + 1) * 32;
            const uint32_t bn = (uint32_t)((c + 1) & 1) * 8448u * 4u;
            #pragma unroll
            for (int p = 0; p < 16; p++) {
                int idx = tid + p * 256;
                int kk = idx & 31;
                int q  = idx >> 5;
                cp4(sb + bn + (uint32_t)(kk * 132 + q) * 4u,
                    &X[(size_t)(m0 + q) * 256 + k0n + kk]);
                cp4(sb + bn + (uint32_t)(4224 + kk * 132 + q) * 4u,
                    &W[(size_t)q * 256 + k0n + kk]);
            }
            asm volatile("cp.async.commit_group;");
        }

        const float* Xs = SA + (c & 1) * 8448;
        const float* Ws = Xs + 4224;

        #pragma unroll 4
        for (int kk = 0; kk < 32; kk++) {
            float4 a0 = *(const float4*)&Xs[kk * 132 + ty * 8];
            float4 a1 = *(const float4*)&Xs[kk * 132 + ty * 8 + 4];
            ulonglong2 p0 = *(const ulonglong2*)&Ws[kk * 132 + tx * 8];
            ulonglong2 p1 = *(const ulonglong2*)&Ws[kk * 132 + tx * 8 + 4];
            unsigned long long bb[4] = {p0.x, p0.y, p1.x, p1.y};
            float a[8] = {a0.x, a0.y, a0.z, a0.w, a1.x, a1.y, a1.z, a1.w};
            #pragma unroll
            for (int i = 0; i < 8; i++) {
                unsigned long long ad = dup2(a[i]);
                #pragma unroll
                for (int j = 0; j < 4; j++) fma2(acc[i][j], ad, bb[j]);
            }
        }
    }

    float bv[8];
    *(float4*)&bv[0] = *(const float4*)&bias[tx * 8];
    *(float4*)&bv[4] = *(const float4*)&bias[tx * 8 + 4];

    float vals[8][8];
    #pragma unroll
    for (int i = 0; i < 8; i++) {
        #pragma unroll
        for (int j = 0; j < 4; j++) {
            float lo, hi;
            unpk(acc[i][j], lo, hi);
            vals[i][2 * j]     = __fadd_rn(lo, bv[2 * j]);
            vals[i][2 * j + 1] = __fadd_rn(hi, bv[2 * j + 1]);
        }
    }

    __syncthreads();

    // pass 1: emulated fp32 norm of raw row (single phase)
    #pragma unroll
    for (int i = 0; i < 8; i++) {
        int rl = ty * 8 + i;
        #pragma unroll
        for (int jj = 0; jj < 8; jj++)
            rbuf[rl * 128 + tx * 8 + jj] = vals[i][jj];
    }
    __syncthreads();
    #pragma unroll
    for (int rr = 0; rr < 16; rr++) {
        int rl = warp * 16 + rr;
        float s = warp_sumsq_row(&rbuf[rl * 128], lane);
        if (lane == 0) rn[rl] = fmaxf(__fsqrt_rn(s), 1e-12f);
    }
    __syncthreads();

    #pragma unroll
    for (int i = 0; i < 8; i++) {
        float nm = rn[ty * 8 + i];
        #pragma unroll
        for (int jj = 0; jj < 8; jj++) vals[i][jj] = __fdiv_rn(vals[i][jj], nm);
    }
    __syncthreads();

    // pass 2: emulated fp32 sum of squares of normalized row -> aux
    #pragma unroll
    for (int i = 0; i < 8; i++) {
        int rl = ty * 8 + i;
        #pragma unroll
        for (int jj = 0; jj < 8; jj++)
            rbuf[rl * 128 + tx * 8 + jj] = vals[i][jj];
    }
    __syncthreads();
    #pragma unroll
    for (int rr = 0; rr < 16; rr++) {
        int rl = warp * 16 + rr;
        float s = warp_sumsq_row(&rbuf[rl * 128], lane);
        if (lane == 0) aux[m0 + rl] = s;
    }

    // fp32 store for rescore: z row-major (coalesced), e transposed
    if (is_z) {
        #pragma unroll
        for (int i = 0; i < 8; i++) {
            int r = m0 + ty * 8 + i;
            *(float4*)&g_zr[(size_t)r * 128 + tx * 8]     = *(float4*)&vals[i][0];
            *(float4*)&g_zr[(size_t)r * 128 + tx * 8 + 4] = *(float4*)&vals[i][4];
        }
    } else {
        #pragma unroll
        for (int jj = 0; jj < 8; jj++) {
            int c = tx * 8 + jj;
            float4 w0 = make_float4(vals[0][jj], vals[1][jj], vals[2][jj], vals[3][jj]);
            float4 w1 = make_float4(vals[4][jj], vals[5][jj], vals[6][jj], vals[7][jj]);
            *(float4*)&g_et[(size_t)c * k + m0 + ty * 8]     = w0;
            *(float4*)&g_et[(size_t)c * k + m0 + ty * 8 + 4] = w1;
        }
    }

    // fp16 copy, row-major [row][feat]
    #pragma unroll
    for (int i = 0; i < 8; i++) {
        int r = m0 + ty * 8 + i;
        uint32_t ph[4];
        #pragma unroll
        for (int j2 = 0; j2 < 4; j2++) {
            __half h0 = __float2half_rn(vals[i][2 * j2]);
            __half h1 = __float2half_rn(vals[i][2 * j2 + 1]);
            ph[j2] = (uint32_t)__half_as_ushort(h0) | ((uint32_t)__half_as_ushort(h1) << 16);
        }
        *(uint4*)&oh[(size_t)r * 128 + tx * 8] = make_uint4(ph[0], ph[1], ph[2], ph[3]);
    }
}

// ============================================================================
// fp16 single-pass HMMA coarse argmax (exact R10): 64 rows/block, 256 threads
// (8 warps = 4M x 2N, warp 16x32), B tiles of 64 codes (x64). 4 blocks/SM.
// Flat branchless top-2 epilogue; near-ties (gap < THETA_S) exactly rescored.
// ============================================================================
#define ROWB   272u              // 128 feats * 2B + 16B pad
#define TILE64 17408u            // 64 rows * 272B
#define SMEM_MMA (3u * TILE64)   // A + 2 B buffers = 52224
#define THETA_S 2.5e-4f

__device__ __forceinline__ void load_tile64(
    const __half* __restrict__ src16, int row0, uint32_t dst, int tid)
{
    #pragma unroll
    for (int p = 0; p < 4; p++) {
        int cid = tid + p * 256;        // 0..1023
        int r   = cid >> 4;             // 0..63
        int ch  = cid & 15;             // 16B chunk
        const char* src = (const char*)src16 + (size_t)(row0 + r) * 256 + ch * 16;
        cp16(dst + (uint32_t)r * ROWB + (uint32_t)ch * 16u, src);
    }
}

__global__ __launch_bounds__(256, 4) void argmin_mma_kernel(
    const __half* __restrict__ zh, const __half* __restrict__ eh,
    int n, int k, int* __restrict__ out_idx)
{
    extern __shared__ char smem[];
    const uint32_t sb = smem_u32(smem);
    const int tid = threadIdx.x, wid = tid >> 5, lane = tid & 31;
    const int mOff = (wid >> 1) * 16;        // 4 M-warps cover 64 rows
    const int nOff = (wid & 1) * 32;         // 2 N-warps cover 64 codes
    const int m0 = blockIdx.x * 64;

    load_tile64(zh, m0, sb, tid);
    load_tile64(eh, 0, sb + TILE64, tid);
    asm volatile("cp.async.commit_group;");

    float b1[2], b2[2];
    int   i1[2];
    #pragma unroll
    for (int s = 0; s < 2; s++) { b1[s] = -1e30f; b2[s] = -1e30f; i1[s] = 0; }

    const uint32_t lrow = (uint32_t)(lane & 15) * ROWB;
    const uint32_t lc16 = (uint32_t)(lane >> 4) * 16u;

    const int T = k >> 6;    // 64 tiles of 64 codes
    for (int t = 0; t < T; t++) {
        if (t + 1 < T) {
            load_tile64(eh, (t + 1) << 6,
                        sb + TILE64 + (uint32_t)((t + 1) & 1) * TILE64, tid);
            asm volatile("cp.async.commit_group;");
            asm volatile("cp.async.wait_group 1;");
        } else {
            asm volatile("cp.async.wait_group 0;");
        }
        __syncthreads();

        const uint32_t Bb = sb + TILE64 + (uint32_t)(t & 1) * TILE64;

        float acc[4][4];
        #pragma unroll
        for (int j = 0; j < 4; j++)
            #pragma unroll
            for (int e = 0; e < 4; e++) acc[j][e] = 0.0f;

        #pragma unroll
        for (int ks = 0; ks < 8; ks++) {
            const uint32_t kb = (uint32_t)ks * 32u + lc16;
            uint32_t ah[4], bh[2][4];
            ldsm4(ah, sb + (uint32_t)mOff * ROWB + lrow + kb);
            #pragma unroll
            for (int jj = 0; jj < 2; jj++)
                ldsm4(bh[jj], Bb + (uint32_t)(nOff + jj * 16) * ROWB + lrow + kb);
            #pragma unroll
            for (int j = 0; j < 4; j++) {
                int jj = j >> 1, sel = j & 1;
                mma16816f(acc[j], ah, bh[jj][sel], bh[jj][sel + 2]);
            }
        }

        // flat branchless top-2 epilogue
        #pragma unroll
        for (int j = 0; j < 4; j++) {
            int col = (t << 6) + nOff + j * 8 + (lane & 3) * 2;
            #pragma unroll
            for (int half = 0; half < 2; half++) {
                int s = half;
                float v0 = acc[j][half * 2 + 0];
                float v1 = acc[j][half * 2 + 1];
                bool g0 = v0 > b1[s];
                b2[s] = fmaxf(b2[s], fminf(v0, b1[s]));
                b1[s] = fmaxf(b1[s], v0);
                i1[s] = g0 ? col : i1[s];
                bool g1 = v1 > b1[s];
                b2[s] = fmaxf(b2[s], fminf(v1, b1[s]));
                b1[s] = fmaxf(b1[s], v1);
                i1[s] = g1 ? (col + 1) : i1[s];
            }
        }
        __syncthreads();   // protect B buffer before next prefetch overwrite
    }

    // merge: 8 contributors per row (2 N-warps x 4 lane-cols); reuse A region
    float* ms1 = (float*)smem;             // 512 floats
    float* ms2 = ms1 + 512;                // 512
    int*   mi1 = (int*)(ms1 + 1024);       // 512
    int contrib = (wid & 1) * 4 + (lane & 3);
    #pragma unroll
    for (int s = 0; s < 2; s++) {
        int rl = mOff + s * 8 + (lane >> 2);
        ms1[rl * 8 + contrib] = b1[s];
        ms2[rl * 8 + contrib] = b2[s];
        mi1[rl * 8 + contrib] = i1[s];
    }
    __syncthreads();
    if (tid < 64) {
        float g1 = -1e30f, g2 = -1e30f; int gi = 0x7fffffff;
        #pragma unroll
        for (int c = 0; c < 8; c++) {
            float v = ms1[tid * 8 + c];
            int  id = mi1[tid * 8 + c];
            if (v > g1 || (v == g1 && id < gi)) { g2 = g1; g1 = v; gi = id; }
            else if (v > g2) g2 = v;
            float w = ms2[tid * 8 + c];
            if (w > g2) g2 = w;
        }
        int row = m0 + tid;
        out_idx[row] = gi;
        if (g1 - g2 < THETA_S) {
            int pos = atomicAdd(&g_fixcount, 1);
            g_fixlist[pos] = row;
        }
    }
}

// ============================================================================
// exact rescore of flagged rows (R10 per-row version — known good)
// ============================================================================
__global__ __launch_bounds__(256) void rescore_kernel(
    const float* __restrict__ zr, const float* __restrict__ et,
    const float* __restrict__ z2a, const float* __restrict__ bcode,
    int n, int k, int* __restrict__ out_idx)
{
    __shared__ float zrow[DH];
    __shared__ float sd[256];
    __shared__ int   sc[256];

    const int tid = threadIdx.x;
    const int cnt = g_fixcount;

    for (int it = blockIdx.x; it < cnt; it += gridDim.x) {
        const int row = g_fixlist[it];
        if (tid < DH) zrow[tid] = zr[(size_t)row * DH + tid];
        __syncthreads();

        float acc[16];
        #pragma unroll
        for (int j = 0; j < 16; j++) acc[j] = 0.0f;

        for (int f = 0; f < DH; f++) {
            float zf = zrow[f];
            const float* er = et + (size_t)f * k + tid;
            #pragma unroll
            for (int j = 0; j < 16; j++)
                acc[j] = __fmaf_rn(zf, er[j * 256], acc[j]);
        }

        float z2r = z2a[row];
        float bd = 3.4e38f; int bc = 0x7fffffff;
        #pragma unroll
        for (int j = 0; j < 16; j++) {
            int c = tid + j * 256;
            float d = __fadd_rn(__fadd_rn(z2r, bcode[c]), -2.0f * acc[j]);
            if (d < bd) { bd = d; bc = c; }
        }
        sd[tid] = bd; sc[tid] = bc;
        __syncthreads();
        for (int off = 128; off; off >>= 1) {
            if (tid < off) {
                float v = sd[tid + off]; int c = sc[tid + off];
                if (v < sd[tid] || (v == sd[tid] && c < sc[tid])) { sd[tid] = v; sc[tid] = c; }
            }
            __syncthreads();
        }
        if (tid == 0) out_idx[row] = sc[0];
        __syncthreads();
    }
}

// ============================================================================
// gather + L2 normalize original codebook rows. One warp per output row.
// ============================================================================
__global__ __launch_bounds__(256) void gather_norm_kernel(
    const float* __restrict__ emb, const int* __restrict__ idx,
    float* __restrict__ out)
{
    const int warp = threadIdx.x >> 5, lane = threadIdx.x & 31;
    const int row = blockIdx.x * 8 + warp;
    const int id = idx[row];

    const float4* src = (const float4*)(emb + (size_t)id * 256);
    float4 v0 = src[lane];
    float4 v1 = src[lane + 32];

    float p = __fmaf_rn(v0.x, v0.x, 0.0f);
    p = __fmaf_rn(v0.y, v0.y, p);
    p = __fmaf_rn(v0.z, v0.z, p);
    p = __fmaf_rn(v0.w, v0.w, p);
    p = __fmaf_rn(v1.x, v1.x, p);
    p = __fmaf_rn(v1.y, v1.y, p);
    p = __fmaf_rn(v1.z, v1.z, p);
    p = __fmaf_rn(v1.w, v1.w, p);
    #pragma unroll
    for (int o = 16; o; o >>= 1) p = __fadd_rn(p, __shfl_xor_sync(0xffffffffu, p, o));

    float nm = fmaxf(__fsqrt_rn(p), 1e-12f);
    v0.x = __fdiv_rn(v0.x, nm); v0.y = __fdiv_rn(v0.y, nm);
    v0.z = __fdiv_rn(v0.z, nm); v0.w = __fdiv_rn(v0.w, nm);
    v1.x = __fdiv_rn(v1.x, nm); v1.y = __fdiv_rn(v1.y, nm);
    v1.z = __fdiv_rn(v1.z, nm); v1.w = __fdiv_rn(v1.w, nm);

    float4* dst = (float4*)(out + (size_t)row * 256);
    dst[lane]      = v0;
    dst[lane + 32] = v1;
}

// ============================================================================
extern "C" void kernel_launch(void* const* d_in, const int* in_sizes, int n_in,
                              void* d_out, int out_size)
{
    const float* z   = (const float*)d_in[0];
    const float* emb = (const float*)d_in[1];
    const float* W   = (const float*)d_in[2];
    const float* b   = (const float*)d_in[3];
    float* out = (float*)d_out;

    const int n = in_sizes[0] / DFULL;   // 65536
    const int k = in_sizes[1] / DFULL;   // 4096

    void *pzr, *pet, *pz2, *pb, *pidx, *pzh, *peh;
    cudaGetSymbolAddress(&pzr, g_zr);
    cudaGetSymbolAddress(&pet, g_et);
    cudaGetSymbolAddress(&pz2, g_z2);
    cudaGetSymbolAddress(&pb, g_b);
    cudaGetSymbolAddress(&pidx, g_idx);
    cudaGetSymbolAddress(&pzh, g_zh);
    cudaGetSymbolAddress(&peh, g_eh);

    const int PROJ_SMEM = 16896 * (int)sizeof(float);   // 67584 B
    cudaFuncSetAttribute(proj_kernel, cudaFuncAttributeMaxDynamicSharedMemorySize, PROJ_SMEM);
    proj_kernel<<<n / 128 + k / 128, 256, PROJ_SMEM>>>(z, emb, W, b, n, k);

    cudaFuncSetAttribute(argmin_mma_kernel, cudaFuncAttributeMaxDynamicSharedMemorySize, SMEM_MMA);
    argmin_mma_kernel<<<n / 64, 256, SMEM_MMA>>>(
        (const __half*)pzh, (const __half*)peh, n, k, (int*)pidx);

    rescore_kernel<<<512, 256>>>((const float*)pzr, (const float*)pet,
                                 (const float*)pz2, (const float*)pb,
                                 n, k, (int*)pidx);

    gather_norm_kernel<<<n / 8, 256>>>(emb, (const int*)pidx, out);
}

// round 17
// speedup vs baseline: 1.1940x; 1.1940x over previous
#include <cuda_runtime.h>
#include <cuda_fp16.h>
#include <cstdint>

#define DFULL 256
#define DH    128
#define NMAX  65536
#define KMAX  4096

// ---------------- device scratch (allocation-free rule) ----------------
__device__ float g_zr[(size_t)NMAX * DH];  // z-hat ROW-major [row][feat] (fp32, rescore)
__device__ float g_et[DH * KMAX];   // emb-hat transposed [feat][code] (fp32, rescore)
__device__ float g_z2[NMAX];        // emulated fp32 sum(zhat^2)
__device__ float g_b [KMAX];        // emulated fp32 sum(ehat^2)
__device__ __half g_zh[(size_t)NMAX * DH];  // fp16 z-hat, row-major [row][feat]
__device__ __half g_eh[(size_t)KMAX * DH];  // fp16 e-hat, row-major [code][feat]
__device__ int   g_idx[NMAX];
__device__ int   g_fixlist[NMAX];
__device__ int   g_fixcount;

// ---------------- helpers ----------------
__device__ __forceinline__ void fma2(unsigned long long &c, unsigned long long a, unsigned long long b) {
    asm("fma.rn.f32x2 %0, %1, %2, %0;" : "+l"(c) : "l"(a), "l"(b));
}
__device__ __forceinline__ unsigned long long dup2(float x) {
    unsigned long long r;
    asm("mov.b64 %0, {%1, %1};" : "=l"(r) : "f"(x));
    return r;
}
__device__ __forceinline__ void unpk(unsigned long long v, float &lo, float &hi) {
    asm("mov.b64 {%0, %1}, %2;" : "=f"(lo), "=f"(hi) : "l"(v));
}
__device__ __forceinline__ uint32_t smem_u32(const void* p) {
    uint32_t a;
    asm("{ .reg .u64 t; cvta.to.shared.u64 t, %1; cvt.u32.u64 %0, t; }" : "=r"(a) : "l"(p));
    return a;
}
__device__ __forceinline__ void cp16(uint32_t dst, const void* src) {
    asm volatile("cp.async.cg.shared.global [%0], [%1], 16;" :: "r"(dst), "l"(src));
}
__device__ __forceinline__ void ldsm4(uint32_t* r, uint32_t addr) {
    asm volatile("ldmatrix.sync.aligned.m8n8.x4.shared.b16 {%0,%1,%2,%3}, [%4];"
                 : "=r"(r[0]), "=r"(r[1]), "=r"(r[2]), "=r"(r[3]) : "r"(addr));
}
__device__ __forceinline__ void mma16816f(float* c, const uint32_t* a, uint32_t b0, uint32_t b1) {
    asm volatile(
        "mma.sync.aligned.m16n8k16.row.col.f32.f16.f16.f32 "
        "{%0,%1,%2,%3}, {%4,%5,%6,%7}, {%8,%9}, {%0,%1,%2,%3};"
        : "+f"(c[0]), "+f"(c[1]), "+f"(c[2]), "+f"(c[3])
        : "r"(a[0]), "r"(a[1]), "r"(a[2]), "r"(a[3]), "r"(b0), "r"(b1));
}

// XLA-GPU-style row reduction of squares (numerics from passing round)
__device__ __forceinline__ float warp_sumsq_row(const float* row, int lane) {
    float x0 = row[lane];
    float x1 = row[lane + 32];
    float x2 = row[lane + 64];
    float x3 = row[lane + 96];
    float p = __fmaf_rn(x0, x0, 0.0f);
    p = __fmaf_rn(x1, x1, p);
    p = __fmaf_rn(x2, x2, p);
    p = __fmaf_rn(x3, x3, p);
    p = __fadd_rn(p, __shfl_down_sync(0xffffffffu, p, 16));
    p = __fadd_rn(p, __shfl_down_sync(0xffffffffu, p, 8));
    p = __fadd_rn(p, __shfl_down_sync(0xffffffffu, p, 4));
    p = __fadd_rn(p, __shfl_down_sync(0xffffffffu, p, 2));
    p = __fadd_rn(p, __shfl_down_sync(0xffffffffu, p, 1));
    return p;
}

// ============================================================================
// fused proj kernel (exact R15 winner): z blocks [0, nbz), emb blocks [nbz,..).
// 128-row blocks, thread tile 8x8, __launch_bounds__(256,2).
// ============================================================================
__global__ __launch_bounds__(256, 2) void proj_kernel(
    const float* __restrict__ Z, const float* __restrict__ E,
    const float* __restrict__ W, const float* __restrict__ bias,
    int n, int k)
{
    extern __shared__ float SA[];       // 16384 floats + rn
    float* Xs = SA;                     // [32][132]
    float* Ws = SA + 4224;
    float* rbuf = SA;                   // [128][128], reused after GEMM
    float* rn = SA + 16384;             // [128]

    const int tid = threadIdx.x;
    const int tx = tid & 15, ty = tid >> 4;
    const int warp = tid >> 5, lane = tid & 31;

    const int nbz = n / 128;
    const bool is_z = (blockIdx.x < (unsigned)nbz);
    const float* X = is_z ? Z : E;
    float* aux   = is_z ? g_z2 : g_b;
    __half* oh   = is_z ? g_zh : g_eh;
    const int m0 = (is_z ? blockIdx.x : (blockIdx.x - nbz)) * 128;

    if (blockIdx.x == 0 && tid == 0) g_fixcount = 0;

    unsigned long long acc[8][4];
    #pragma unroll
    for (int i = 0; i < 8; i++)
        #pragma unroll
        for (int j = 0; j < 4; j++) acc[i][j] = 0ull;

    for (int k0 = 0; k0 < 256; k0 += 32) {
        __syncthreads();
        #pragma unroll
        for (int p = 0; p < 16; p++) {
            int idx = tid + p * 256;
            int kk = idx & 31;
            int q  = idx >> 5;
            Xs[kk * 132 + q] = X[(size_t)(m0 + q) * 256 + k0 + kk];
            Ws[kk * 132 + q] = W[(size_t)q * 256 + k0 + kk];
        }
        __syncthreads();

        #pragma unroll 4
        for (int kk = 0; kk < 32; kk++) {
            float4 a0 = *(const float4*)&Xs[kk * 132 + ty * 8];
            float4 a1 = *(const float4*)&Xs[kk * 132 + ty * 8 + 4];
            ulonglong2 p0 = *(const ulonglong2*)&Ws[kk * 132 + tx * 8];
            ulonglong2 p1 = *(const ulonglong2*)&Ws[kk * 132 + tx * 8 + 4];
            unsigned long long bb[4] = {p0.x, p0.y, p1.x, p1.y};
            float a[8] = {a0.x, a0.y, a0.z, a0.w, a1.x, a1.y, a1.z, a1.w};
            #pragma unroll
            for (int i = 0; i < 8; i++) {
                unsigned long long ad = dup2(a[i]);
                #pragma unroll
                for (int j = 0; j < 4; j++) fma2(acc[i][j], ad, bb[j]);
            }
        }
    }

    float bv[8];
    *(float4*)&bv[0] = *(const float4*)&bias[tx * 8];
    *(float4*)&bv[4] = *(const float4*)&bias[tx * 8 + 4];

    float vals[8][8];
    #pragma unroll
    for (int i = 0; i < 8; i++) {
        #pragma unroll
        for (int j = 0; j < 4; j++) {
            float lo, hi;
            unpk(acc[i][j], lo, hi);
            vals[i][2 * j]     = __fadd_rn(lo, bv[2 * j]);
            vals[i][2 * j + 1] = __fadd_rn(hi, bv[2 * j + 1]);
        }
    }

    __syncthreads();

    // pass 1: emulated fp32 norm of raw row (single phase)
    #pragma unroll
    for (int i = 0; i < 8; i++) {
        int rl = ty * 8 + i;
        #pragma unroll
        for (int jj = 0; jj < 8; jj++)
            rbuf[rl * 128 + tx * 8 + jj] = vals[i][jj];
    }
    __syncthreads();
    #pragma unroll
    for (int rr = 0; rr < 16; rr++) {
        int rl = warp * 16 + rr;
        float s = warp_sumsq_row(&rbuf[rl * 128], lane);
        if (lane == 0) rn[rl] = fmaxf(__fsqrt_rn(s), 1e-12f);
    }
    __syncthreads();

    #pragma unroll
    for (int i = 0; i < 8; i++) {
        float nm = rn[ty * 8 + i];
        #pragma unroll
        for (int jj = 0; jj < 8; jj++) vals[i][jj] = __fdiv_rn(vals[i][jj], nm);
    }
    __syncthreads();

    // pass 2: emulated fp32 sum of squares of normalized row -> aux
    #pragma unroll
    for (int i = 0; i < 8; i++) {
        int rl = ty * 8 + i;
        #pragma unroll
        for (int jj = 0; jj < 8; jj++)
            rbuf[rl * 128 + tx * 8 + jj] = vals[i][jj];
    }
    __syncthreads();
    #pragma unroll
    for (int rr = 0; rr < 16; rr++) {
        int rl = warp * 16 + rr;
        float s = warp_sumsq_row(&rbuf[rl * 128], lane);
        if (lane == 0) aux[m0 + rl] = s;
    }

    // fp32 store for rescore: z row-major (coalesced), e transposed
    if (is_z) {
        #pragma unroll
        for (int i = 0; i < 8; i++) {
            int r = m0 + ty * 8 + i;
            *(float4*)&g_zr[(size_t)r * 128 + tx * 8]     = *(float4*)&vals[i][0];
            *(float4*)&g_zr[(size_t)r * 128 + tx * 8 + 4] = *(float4*)&vals[i][4];
        }
    } else {
        #pragma unroll
        for (int jj = 0; jj < 8; jj++) {
            int c = tx * 8 + jj;
            float4 w0 = make_float4(vals[0][jj], vals[1][jj], vals[2][jj], vals[3][jj]);
            float4 w1 = make_float4(vals[4][jj], vals[5][jj], vals[6][jj], vals[7][jj]);
            *(float4*)&g_et[(size_t)c * k + m0 + ty * 8]     = w0;
            *(float4*)&g_et[(size_t)c * k + m0 + ty * 8 + 4] = w1;
        }
    }

    // fp16 copy, row-major [row][feat]
    #pragma unroll
    for (int i = 0; i < 8; i++) {
        int r = m0 + ty * 8 + i;
        uint32_t ph[4];
        #pragma unroll
        for (int j2 = 0; j2 < 4; j2++) {
            __half h0 = __float2half_rn(vals[i][2 * j2]);
            __half h1 = __float2half_rn(vals[i][2 * j2 + 1]);
            ph[j2] = (uint32_t)__half_as_ushort(h0) | ((uint32_t)__half_as_ushort(h1) << 16);
        }
        *(uint4*)&oh[(size_t)r * 128 + tx * 8] = make_uint4(ph[0], ph[1], ph[2], ph[3]);
    }
}

// ============================================================================
// fp16 single-pass HMMA coarse argmax (exact R10): 64 rows/block, 256 threads
// (8 warps = 4M x 2N, warp 16x32), B tiles of 64 codes (x64). 4 blocks/SM.
// Flat branchless top-2 epilogue; near-ties (gap < THETA_S) exactly rescored.
// ============================================================================
#define ROWB   272u              // 128 feats * 2B + 16B pad
#define TILE64 17408u            // 64 rows * 272B
#define SMEM_MMA (3u * TILE64)   // A + 2 B buffers = 52224
#define THETA_S 2.5e-4f

__device__ __forceinline__ void load_tile64(
    const __half* __restrict__ src16, int row0, uint32_t dst, int tid)
{
    #pragma unroll
    for (int p = 0; p < 4; p++) {
        int cid = tid + p * 256;        // 0..1023
        int r   = cid >> 4;             // 0..63
        int ch  = cid & 15;             // 16B chunk
        const char* src = (const char*)src16 + (size_t)(row0 + r) * 256 + ch * 16;
        cp16(dst + (uint32_t)r * ROWB + (uint32_t)ch * 16u, src);
    }
}

__global__ __launch_bounds__(256, 4) void argmin_mma_kernel(
    const __half* __restrict__ zh, const __half* __restrict__ eh,
    int n, int k, int* __restrict__ out_idx)
{
    extern __shared__ char smem[];
    const uint32_t sb = smem_u32(smem);
    const int tid = threadIdx.x, wid = tid >> 5, lane = tid & 31;
    const int mOff = (wid >> 1) * 16;        // 4 M-warps cover 64 rows
    const int nOff = (wid & 1) * 32;         // 2 N-warps cover 64 codes
    const int m0 = blockIdx.x * 64;

    load_tile64(zh, m0, sb, tid);
    load_tile64(eh, 0, sb + TILE64, tid);
    asm volatile("cp.async.commit_group;");

    float b1[2], b2[2];
    int   i1[2];
    #pragma unroll
    for (int s = 0; s < 2; s++) { b1[s] = -1e30f; b2[s] = -1e30f; i1[s] = 0; }

    const uint32_t lrow = (uint32_t)(lane & 15) * ROWB;
    const uint32_t lc16 = (uint32_t)(lane >> 4) * 16u;

    const int T = k >> 6;    // 64 tiles of 64 codes
    for (int t = 0; t < T; t++) {
        if (t + 1 < T) {
            load_tile64(eh, (t + 1) << 6,
                        sb + TILE64 + (uint32_t)((t + 1) & 1) * TILE64, tid);
            asm volatile("cp.async.commit_group;");
            asm volatile("cp.async.wait_group 1;");
        } else {
            asm volatile("cp.async.wait_group 0;");
        }
        __syncthreads();

        const uint32_t Bb = sb + TILE64 + (uint32_t)(t & 1) * TILE64;

        float acc[4][4];
        #pragma unroll
        for (int j = 0; j < 4; j++)
            #pragma unroll
            for (int e = 0; e < 4; e++) acc[j][e] = 0.0f;

        #pragma unroll
        for (int ks = 0; ks < 8; ks++) {
            const uint32_t kb = (uint32_t)ks * 32u + lc16;
            uint32_t ah[4], bh[2][4];
            ldsm4(ah, sb + (uint32_t)mOff * ROWB + lrow + kb);
            #pragma unroll
            for (int jj = 0; jj < 2; jj++)
                ldsm4(bh[jj], Bb + (uint32_t)(nOff + jj * 16) * ROWB + lrow + kb);
            #pragma unroll
            for (int j = 0; j < 4; j++) {
                int jj = j >> 1, sel = j & 1;
                mma16816f(acc[j], ah, bh[jj][sel], bh[jj][sel + 2]);
            }
        }

        // flat branchless top-2 epilogue
        #pragma unroll
        for (int j = 0; j < 4; j++) {
            int col = (t << 6) + nOff + j * 8 + (lane & 3) * 2;
            #pragma unroll
            for (int half = 0; half < 2; half++) {
                int s = half;
                float v0 = acc[j][half * 2 + 0];
                float v1 = acc[j][half * 2 + 1];
                bool g0 = v0 > b1[s];
                b2[s] = fmaxf(b2[s], fminf(v0, b1[s]));
                b1[s] = fmaxf(b1[s], v0);
                i1[s] = g0 ? col : i1[s];
                bool g1 = v1 > b1[s];
                b2[s] = fmaxf(b2[s], fminf(v1, b1[s]));
                b1[s] = fmaxf(b1[s], v1);
                i1[s] = g1 ? (col + 1) : i1[s];
            }
        }
        __syncthreads();   // protect B buffer before next prefetch overwrite
    }

    // merge: 8 contributors per row (2 N-warps x 4 lane-cols); reuse A region
    float* ms1 = (float*)smem;             // 512 floats
    float* ms2 = ms1 + 512;                // 512
    int*   mi1 = (int*)(ms1 + 1024);       // 512
    int contrib = (wid & 1) * 4 + (lane & 3);
    #pragma unroll
    for (int s = 0; s < 2; s++) {
        int rl = mOff + s * 8 + (lane >> 2);
        ms1[rl * 8 + contrib] = b1[s];
        ms2[rl * 8 + contrib] = b2[s];
        mi1[rl * 8 + contrib] = i1[s];
    }
    __syncthreads();
    if (tid < 64) {
        float g1 = -1e30f, g2 = -1e30f; int gi = 0x7fffffff;
        #pragma unroll
        for (int c = 0; c < 8; c++) {
            float v = ms1[tid * 8 + c];
            int  id = mi1[tid * 8 + c];
            if (v > g1 || (v == g1 && id < gi)) { g2 = g1; g1 = v; gi = id; }
            else if (v > g2) g2 = v;
            float w = ms2[tid * 8 + c];
            if (w > g2) g2 = w;
        }
        int row = m0 + tid;
        out_idx[row] = gi;
        if (g1 - g2 < THETA_S) {
            int pos = atomicAdd(&g_fixcount, 1);
            g_fixlist[pos] = row;
        }
    }
}

// ============================================================================
// exact rescore, 4 flagged rows per block sharing each et LDG via registers.
// Per-(row,code) numerics bit-identical to the R10 chain: ascending-f
// single-acc fp32 FMA; d = fl(fl(z2+b)-2*acc); ascending-c strict < and
// index-tie-break tree (lowest code wins).
// ============================================================================
__global__ __launch_bounds__(256) void rescore_kernel(
    const float* __restrict__ zr, const float* __restrict__ et,
    const float* __restrict__ z2a, const float* __restrict__ bcode,
    int n, int k, int* __restrict__ out_idx)
{
    __shared__ float zs[4][DH];      // 2 KB
    __shared__ float z2s[4];
    __shared__ int   rows[4];
    __shared__ float sd[4][256];     // 4 KB
    __shared__ int   sc[4][256];     // 4 KB

    const int tid = threadIdx.x;
    const int cnt = g_fixcount;
    const int nb = (cnt + 3) >> 2;

    for (int bi = blockIdx.x; bi < nb; bi += gridDim.x) {
        __syncthreads();   // protect zs/rows from previous iteration readers
        if (tid < 4) {
            int ii = bi * 4 + tid;
            rows[tid] = (ii < cnt) ? g_fixlist[ii] : -1;
            z2s[tid] = 0.0f;
        }
        __syncthreads();
        // stage 4 z rows (512 floats, 2 per thread)
        #pragma unroll
        for (int p = 0; p < 2; p++) {
            int idx = tid + p * 256;
            int r = idx >> 7, f = idx & 127;
            int src = (rows[r] >= 0) ? rows[r] : 0;
            zs[r][f] = zr[(size_t)src * 128 + f];
        }
        if (tid < 4 && rows[tid] >= 0) z2s[tid] = z2a[rows[tid]];
        __syncthreads();

        float acc[4][16];
        #pragma unroll
        for (int r = 0; r < 4; r++)
            #pragma unroll
            for (int j = 0; j < 16; j++) acc[r][j] = 0.0f;

        for (int f = 0; f < DH; f++) {
            float zf0 = zs[0][f], zf1 = zs[1][f], zf2 = zs[2][f], zf3 = zs[3][f];
            const float* er = et + (size_t)f * k + tid;
            #pragma unroll
            for (int j = 0; j < 16; j++) {
                float ev = er[j * 256];          // ONE LDG serves 4 rows
                acc[0][j] = __fmaf_rn(zf0, ev, acc[0][j]);
                acc[1][j] = __fmaf_rn(zf1, ev, acc[1][j]);
                acc[2][j] = __fmaf_rn(zf2, ev, acc[2][j]);
                acc[3][j] = __fmaf_rn(zf3, ev, acc[3][j]);
            }
        }

        // per-thread argmin per row (ascending c; strict < keeps lowest)
        #pragma unroll
        for (int r = 0; r < 4; r++) {
            float z2r = z2s[r];
            float bd = 3.4e38f; int bc = 0x7fffffff;
            #pragma unroll
            for (int j = 0; j < 16; j++) {
                int c = tid + j * 256;
                float d = __fadd_rn(__fadd_rn(z2r, bcode[c]), -2.0f * acc[r][j]);
                if (d < bd) { bd = d; bc = c; }
            }
            sd[r][tid] = bd; sc[r][tid] = bc;
        }
        __syncthreads();
        for (int off = 128; off; off >>= 1) {
            if (tid < off) {
                #pragma unroll
                for (int r = 0; r < 4; r++) {
                    float v = sd[r][tid + off]; int c = sc[r][tid + off];
                    if (v < sd[r][tid] || (v == sd[r][tid] && c < sc[r][tid])) {
                        sd[r][tid] = v; sc[r][tid] = c;
                    }
                }
            }
            __syncthreads();
        }
        if (tid < 4 && rows[tid] >= 0) out_idx[rows[tid]] = sc[tid][0];
    }
}

// ============================================================================
// gather + L2 normalize original codebook rows. One warp per output row.
// ============================================================================
__global__ __launch_bounds__(256) void gather_norm_kernel(
    const float* __restrict__ emb, const int* __restrict__ idx,
    float* __restrict__ out)
{
    const int warp = threadIdx.x >> 5, lane = threadIdx.x & 31;
    const int row = blockIdx.x * 8 + warp;
    const int id = idx[row];

    const float4* src = (const float4*)(emb + (size_t)id * 256);
    float4 v0 = src[lane];
    float4 v1 = src[lane + 32];

    float p = __fmaf_rn(v0.x, v0.x, 0.0f);
    p = __fmaf_rn(v0.y, v0.y, p);
    p = __fmaf_rn(v0.z, v0.z, p);
    p = __fmaf_rn(v0.w, v0.w, p);
    p = __fmaf_rn(v1.x, v1.x, p);
    p = __fmaf_rn(v1.y, v1.y, p);
    p = __fmaf_rn(v1.z, v1.z, p);
    p = __fmaf_rn(v1.w, v1.w, p);
    #pragma unroll
    for (int o = 16; o; o >>= 1) p = __fadd_rn(p, __shfl_xor_sync(0xffffffffu, p, o));

    float nm = fmaxf(__fsqrt_rn(p), 1e-12f);
    v0.x = __fdiv_rn(v0.x, nm); v0.y = __fdiv_rn(v0.y, nm);
    v0.z = __fdiv_rn(v0.z, nm); v0.w = __fdiv_rn(v0.w, nm);
    v1.x = __fdiv_rn(v1.x, nm); v1.y = __fdiv_rn(v1.y, nm);
    v1.z = __fdiv_rn(v1.z, nm); v1.w = __fdiv_rn(v1.w, nm);

    float4* dst = (float4*)(out + (size_t)row * 256);
    dst[lane]      = v0;
    dst[lane + 32] = v1;
}

// ============================================================================
extern "C" void kernel_launch(void* const* d_in, const int* in_sizes, int n_in,
                              void* d_out, int out_size)
{
    const float* z   = (const float*)d_in[0];
    const float* emb = (const float*)d_in[1];
    const float* W   = (const float*)d_in[2];
    const float* b   = (const float*)d_in[3];
    float* out = (float*)d_out;

    const int n = in_sizes[0] / DFULL;   // 65536
    const int k = in_sizes[1] / DFULL;   // 4096

    void *pzr, *pet, *pz2, *pb, *pidx, *pzh, *peh;
    cudaGetSymbolAddress(&pzr, g_zr);
    cudaGetSymbolAddress(&pet, g_et);
    cudaGetSymbolAddress(&pz2, g_z2);
    cudaGetSymbolAddress(&pb, g_b);
    cudaGetSymbolAddress(&pidx, g_idx);
    cudaGetSymbolAddress(&pzh, g_zh);
    cudaGetSymbolAddress(&peh, g_eh);

    const int PROJ_SMEM = (16384 + 128) * (int)sizeof(float);   // 66 KB
    cudaFuncSetAttribute(proj_kernel, cudaFuncAttributeMaxDynamicSharedMemorySize, PROJ_SMEM);
    proj_kernel<<<n / 128 + k / 128, 256, PROJ_SMEM>>>(z, emb, W, b, n, k);

    cudaFuncSetAttribute(argmin_mma_kernel, cudaFuncAttributeMaxDynamicSharedMemorySize, SMEM_MMA);
    argmin_mma_kernel<<<n / 64, 256, SMEM_MMA>>>(
        (const __half*)pzh, (const __half*)peh, n, k, (int*)pidx);

    rescore_kernel<<<296, 256>>>((const float*)pzr, (const float*)pet,
                                 (const float*)pz2, (const float*)pb,
                                 n, k, (int*)pidx);

    gather_norm_kernel<<<n / 8, 256>>>(emb, (const int*)pidx, out);
}